// round 2
// baseline (speedup 1.0000x reference)
#include <cuda_runtime.h>
#include <math.h>

#define NS 512   // sentences
#define NQ 512   // queries
#define ND 256   // docs per sentence
#define NF 50    // features
#define QP 52    // padded feature stride (float4-aligned)
#define STP 260  // senT row stride in floats (float4-aligned, odd/4 banks)
#define NOUT 200

// Global scratch (static __device__ arrays — no allocation in kernel_launch).
// g_S: per-sentence sXY stored COLUMN-major: g_S[b][j][i], j=0..511, i=0..255
__device__ float g_S[67108864];   // 512*512*256 floats = 268 MB
// g_T: per-sentence T = sQ2D^T @ sen, padded rows of QP
__device__ float g_T[13631488];   // 512*512*52 floats = 54.5 MB

#define SMEM_FLOATS (NQ*QP + ND*QP + NF*STP + 152 + NQ + ND + ND + NQ + NQ + ND)
#define SMEM_BYTES  (SMEM_FLOATS * 4)

__global__ __launch_bounds__(256, 1)
void cross_attn_kernel(const float* __restrict__ query,
                       const float* __restrict__ doc,
                       const float* __restrict__ W,
                       float* __restrict__ out)
{
    extern __shared__ float sm[];
    float* s_q      = sm;                  // [NQ][QP]  raw query (pad zeroed)
    float* s_sen4   = s_q + NQ*QP;         // [ND][QP]  raw sen (pad zeroed)
    float* s_senT   = s_sen4 + ND*QP;      // [NF][STP] sen^T * w3
    float* s_w      = s_senT + NF*STP;     // [152]     w1|w2|w3
    float* s_qterm  = s_w + 152;           // [NQ]
    float* s_rowmax = s_qterm + NQ;        // [ND]
    float* s_rowinv = s_rowmax + ND;       // [ND]
    float* s_colmax = s_rowinv + ND;       // [NQ]
    float* s_colinv = s_colmax + NQ;       // [NQ]
    float* s_senw1  = s_colinv + NQ;       // [ND]

    const int tid = threadIdx.x;
    const int b   = blockIdx.x;
    float* Scol = g_S + (size_t)b * NQ * ND;
    float* Tg   = g_T + (size_t)b * NQ * QP;

    // ---------------- load phase ----------------
    for (int i = tid; i < 150; i += 256) s_w[i] = W[i];

    for (int idx = tid; idx < NQ*NF; idx += 256) {
        int j = idx / NF, k = idx - j*NF;
        s_q[j*QP + k] = query[idx];
    }
    for (int j = tid; j < NQ; j += 256) { s_q[j*QP+50] = 0.f; s_q[j*QP+51] = 0.f; }

    const float* sen = doc + (size_t)b * ND * NF;
    for (int idx = tid; idx < ND*NF; idx += 256) {
        int i = idx / NF, k = idx - i*NF;
        s_sen4[i*QP + k] = sen[idx];
    }
    { int i = tid; s_sen4[i*QP+50] = 0.f; s_sen4[i*QP+51] = 0.f; }
    __syncthreads();

    // senT[k][i] = sen[i][k] * w3[k]; qterm[j] = q[j].w2; senw1[i] = sen[i].w1
    for (int idx = tid; idx < NF*ND; idx += 256) {
        int k = idx >> 8, i = idx & 255;
        s_senT[k*STP + i] = s_sen4[i*QP + k] * s_w[100 + k];
    }
    for (int j = tid; j < NQ; j += 256) {
        float a = 0.f;
        #pragma unroll
        for (int k = 0; k < NF; k++) a += s_q[j*QP + k] * s_w[50 + k];
        s_qterm[j] = a;
    }
    {
        const int i = tid;
        float a = 0.f;
        #pragma unroll
        for (int k = 0; k < NF; k++) a += s_sen4[i*QP + k] * s_w[k];
        s_senw1[i] = a;
    }
    __syncthreads();

    // ---------------- pass 1: S[j][i] = senw1[i] + qterm[j] + sum_k senT[k][i]*q[j][k]
    // Register-tiled GEMM: thread = (tx: 4 consecutive i via float4 A, ty: 16 j's stride 16)
    {
        const int tx = tid & 15, ty = tid >> 4;
        for (int jc = 0; jc < 2; jc++) {
            for (int ib = 0; ib < 4; ib++) {
                const int i0 = ib*64 + tx*4;
                const int jb = jc*256 + ty;   // j = jb + jj*16
                float acc[16][4];
                #pragma unroll
                for (int jj = 0; jj < 16; jj++) {
                    acc[jj][0]=0.f; acc[jj][1]=0.f; acc[jj][2]=0.f; acc[jj][3]=0.f;
                }
                #pragma unroll 2
                for (int k = 0; k < NF; k++) {
                    const float4 a4 = *(const float4*)(s_senT + k*STP + i0);
                    #pragma unroll
                    for (int jj = 0; jj < 16; jj++) {
                        const float bv = s_q[(jb + jj*16)*QP + k];
                        acc[jj][0] += a4.x * bv;
                        acc[jj][1] += a4.y * bv;
                        acc[jj][2] += a4.z * bv;
                        acc[jj][3] += a4.w * bv;
                    }
                }
                const float e0 = s_senw1[i0+0], e1 = s_senw1[i0+1];
                const float e2 = s_senw1[i0+2], e3 = s_senw1[i0+3];
                #pragma unroll
                for (int jj = 0; jj < 16; jj++) {
                    const int j = jb + jj*16;
                    const float qt = s_qterm[j];
                    float4 v;
                    v.x = acc[jj][0] + qt + e0;
                    v.y = acc[jj][1] + qt + e1;
                    v.z = acc[jj][2] + qt + e2;
                    v.w = acc[jj][3] + qt + e3;
                    *(float4*)(Scol + j*ND + i0) = v;   // coalesced col-major store
                }
            }
        }
    }
    __syncthreads();

    // ---------------- pass 2: row stats (softmax axis=1, over j). thread = row i
    {
        const int i = tid;
        float m = -3.0e38f;
        #pragma unroll 4
        for (int j = 0; j < NQ; j++) m = fmaxf(m, Scol[j*ND + i]);
        float s = 0.f;
        #pragma unroll 4
        for (int j = 0; j < NQ; j++) s += __expf(Scol[j*ND + i] - m);
        s_rowmax[i] = m;
        s_rowinv[i] = 1.f / s;
    }

    // ---------------- pass 3: col stats (softmax axis=0, over i). warp per column
    {
        const int lane = tid & 31, wrp = tid >> 5;
        for (int j = wrp; j < NQ; j += 8) {
            const float* col = Scol + j*ND;
            float v[8];
            #pragma unroll
            for (int r = 0; r < 8; r++) v[r] = col[lane + 32*r];
            float m = v[0];
            #pragma unroll
            for (int r = 1; r < 8; r++) m = fmaxf(m, v[r]);
            #pragma unroll
            for (int o = 16; o > 0; o >>= 1) m = fmaxf(m, __shfl_xor_sync(0xffffffffu, m, o));
            float s = 0.f;
            #pragma unroll
            for (int r = 0; r < 8; r++) s += __expf(v[r] - m);
            #pragma unroll
            for (int o = 16; o > 0; o >>= 1) s += __shfl_xor_sync(0xffffffffu, s, o);
            if (lane == 0) { s_colmax[j] = m; s_colinv[j] = 1.f / s; }
        }
    }
    __syncthreads();

    // ---------------- pass 5: T[j][:] = sum_i sQ2D[i][j] * sen[i][:]  (thread = column j)
    for (int half = 0; half < 2; half++) {
        const int j = tid + half*256;
        const float4* col4 = (const float4*)(Scol + j*ND);
        float acc[QP];
        #pragma unroll
        for (int k = 0; k < QP; k++) acc[k] = 0.f;
        #pragma unroll 2
        for (int i4 = 0; i4 < ND/4; i4++) {
            const float4 v4 = col4[i4];
            const float vv[4] = { v4.x, v4.y, v4.z, v4.w };
            #pragma unroll
            for (int u = 0; u < 4; u++) {
                const int i = i4*4 + u;
                const float qf = __expf(vv[u] - s_rowmax[i]) * s_rowinv[i];
                const float4* srow = (const float4*)(s_sen4 + i*QP);  // LDS.128 broadcast
                #pragma unroll
                for (int kc = 0; kc < 13; kc++) {
                    const float4 sv = srow[kc];
                    acc[4*kc+0] += qf * sv.x;
                    acc[4*kc+1] += qf * sv.y;
                    acc[4*kc+2] += qf * sv.z;
                    acc[4*kc+3] += qf * sv.w;
                }
            }
        }
        float4* tdst = (float4*)(Tg + j*QP);
        #pragma unroll
        for (int kc = 0; kc < 13; kc++) {
            float4 v; v.x = acc[4*kc]; v.y = acc[4*kc+1]; v.z = acc[4*kc+2]; v.w = acc[4*kc+3];
            tdst[kc] = v;
        }
    }
    __syncthreads();

    // ---------------- fused pass 4+6: one sweep over S computes BOTH
    //   aD2Q[i][:] = sum_j sD2Q[i][j]*query[j][:]   and
    //   aQ2D[i][:] = sum_j sD2Q[i][j]*T[j][:]
    {
        const int i = tid;
        float acc1[QP], acc2[QP];
        #pragma unroll
        for (int k = 0; k < QP; k++) { acc1[k] = 0.f; acc2[k] = 0.f; }
        #pragma unroll 2
        for (int j = 0; j < NQ; j++) {
            const float v = Scol[j*ND + i];                 // coalesced
            const float p = __expf(v - s_colmax[j]) * s_colinv[j];
            const float4* q4 = (const float4*)(s_q + j*QP); // LDS.128 broadcast
            const float4* t4 = (const float4*)(Tg + j*QP);  // LDG.128 broadcast (L2)
            #pragma unroll
            for (int kc = 0; kc < 13; kc++) {
                const float4 qv = q4[kc];
                const float4 tv = t4[kc];
                acc1[4*kc+0] += p * qv.x;  acc1[4*kc+1] += p * qv.y;
                acc1[4*kc+2] += p * qv.z;  acc1[4*kc+3] += p * qv.w;
                acc2[4*kc+0] += p * tv.x;  acc2[4*kc+1] += p * tv.y;
                acc2[4*kc+2] += p * tv.z;  acc2[4*kc+3] += p * tv.w;
            }
        }

        // ---------------- output: [sen | aD2Q | sen*aD2Q | sen*aQ2D]  (200 floats/row)
        float senr[QP];
        const float4* srow = (const float4*)(s_sen4 + i*QP);
        #pragma unroll
        for (int kc = 0; kc < 13; kc++) {
            const float4 sv = srow[kc];
            senr[4*kc+0]=sv.x; senr[4*kc+1]=sv.y; senr[4*kc+2]=sv.z; senr[4*kc+3]=sv.w;
        }
        float* orow = out + ((size_t)b*ND + i) * NOUT;
        #pragma unroll
        for (int c4 = 0; c4 < NOUT/4; c4++) {
            float vals[4];
            #pragma unroll
            for (int u = 0; u < 4; u++) {
                const int c = 4*c4 + u;
                float x;
                if      (c < 50)  x = senr[c];
                else if (c < 100) x = acc1[c-50];
                else if (c < 150) x = senr[c-100] * acc1[c-100];
                else              x = senr[c-150] * acc2[c-150];
                vals[u] = x;
            }
            float4 vo; vo.x=vals[0]; vo.y=vals[1]; vo.z=vals[2]; vo.w=vals[3];
            *(float4*)(orow + 4*c4) = vo;
        }
    }
}

extern "C" void kernel_launch(void* const* d_in, const int* in_sizes, int n_in,
                              void* d_out, int out_size)
{
    // Identify inputs by element count (robust to ordering):
    //   query = 512*50 = 25600, doc = 512*256*50 = 6553600, W = 150
    const float* query = nullptr;
    const float* doc   = nullptr;
    const float* Wp    = nullptr;
    for (int i = 0; i < n_in; i++) {
        if      (in_sizes[i] == 150)       Wp    = (const float*)d_in[i];
        else if (in_sizes[i] == NQ*NF)     query = (const float*)d_in[i];
        else                               doc   = (const float*)d_in[i];
    }

    cudaFuncSetAttribute(cross_attn_kernel,
                         cudaFuncAttributeMaxDynamicSharedMemorySize, SMEM_BYTES);
    cross_attn_kernel<<<NS, 256, SMEM_BYTES>>>(query, doc, Wp, (float*)d_out);
}

// round 3
// speedup vs baseline: 1.0437x; 1.0437x over previous
#include <cuda_runtime.h>
#include <math.h>

#define NS 512   // sentences
#define NQ 512   // queries
#define ND 256   // docs per sentence
#define NF 50    // features
#define QP 52    // padded feature stride (float4/16B-aligned rows: 208 B)
#define STP 260  // senT row stride in floats (1040 B, 16B-aligned)
#define NOUT 200

// Global scratch (static __device__ arrays — no allocation in kernel_launch).
// g_S: per-sentence sXY stored COLUMN-major: g_S[b][j][i]
__device__ float g_S[67108864];   // 512*512*256 floats = 268 MB
// g_T: per-sentence T = sQ2D^T @ sen, padded rows of QP
__device__ float g_T[13631488];   // 512*512*52 floats

#define SMEM_FLOATS (NQ*QP + ND*QP + NF*STP + 152 + NQ + ND + ND + NQ + NQ + ND)
#define SMEM_BYTES  (SMEM_FLOATS * 4)

typedef unsigned long long u64;

// Packed f32x2 helpers (Blackwell dual-FMA pipe)
__device__ __forceinline__ u64 pack2(float x, float y) {
    u64 r; asm("mov.b64 %0, {%1, %2};" : "=l"(r) : "f"(x), "f"(y)); return r;
}
__device__ __forceinline__ u64 fma2(u64 a, u64 b, u64 c) {
    u64 d; asm("fma.rn.f32x2 %0, %1, %2, %3;" : "=l"(d) : "l"(a), "l"(b), "l"(c)); return d;
}
__device__ __forceinline__ float2 unpack2(u64 v) {
    float lo, hi; asm("mov.b64 {%0, %1}, %2;" : "=f"(lo), "=f"(hi) : "l"(v));
    return make_float2(lo, hi);
}

__global__ __launch_bounds__(512, 1)
void cross_attn_kernel(const float* __restrict__ query,
                       const float* __restrict__ doc,
                       const float* __restrict__ W,
                       float* __restrict__ out)
{
    extern __shared__ float sm[];
    float* s_q      = sm;                  // [NQ][QP]  raw query (pad zeroed)
    float* s_sen4   = s_q + NQ*QP;         // [ND][QP]  raw sen (pad zeroed)
    float* s_senT   = s_sen4 + ND*QP;      // [NF][STP] sen^T * w3
    float* s_w      = s_senT + NF*STP;     // [152]     w1|w2|w3
    float* s_qterm  = s_w + 152;           // [NQ]
    float* s_rowmax = s_qterm + NQ;        // [ND]
    float* s_rowinv = s_rowmax + ND;       // [ND]
    float* s_colmax = s_rowinv + ND;       // [NQ]
    float* s_colinv = s_colmax + NQ;       // [NQ]
    float* s_senw1  = s_colinv + NQ;       // [ND]

    const int tid = threadIdx.x;           // 0..511
    const int b   = blockIdx.x;
    float* Scol = g_S + (size_t)b * NQ * ND;
    float* Tg   = g_T + (size_t)b * NQ * QP;

    // ---------------- load phase ----------------
    if (tid < 150) s_w[tid] = W[tid];

    for (int idx = tid; idx < NQ*NF; idx += 512) {
        int j = idx / NF, k = idx - j*NF;
        s_q[j*QP + k] = query[idx];
    }
    { int j = tid; s_q[j*QP+50] = 0.f; s_q[j*QP+51] = 0.f; }

    const float* sen = doc + (size_t)b * ND * NF;
    for (int idx = tid; idx < ND*NF; idx += 512) {
        int i = idx / NF, k = idx - i*NF;
        s_sen4[i*QP + k] = sen[idx];
    }
    if (tid < ND) { s_sen4[tid*QP+50] = 0.f; s_sen4[tid*QP+51] = 0.f; }
    __syncthreads();

    // senT[k][i] = sen[i][k]*w3[k]; qterm[j] = q[j].w2; senw1[i] = sen[i].w1
    for (int idx = tid; idx < NF*ND; idx += 512) {
        int k = idx >> 8, i = idx & 255;
        s_senT[k*STP + i] = s_sen4[i*QP + k] * s_w[100 + k];
    }
    {
        const int j = tid;
        float a = 0.f;
        #pragma unroll
        for (int k = 0; k < NF; k++) a += s_q[j*QP + k] * s_w[50 + k];
        s_qterm[j] = a;
    }
    if (tid < ND) {
        const int i = tid;
        float a = 0.f;
        #pragma unroll
        for (int k = 0; k < NF; k++) a += s_sen4[i*QP + k] * s_w[k];
        s_senw1[i] = a;
    }
    __syncthreads();

    // ---------------- pass 1: S[j][i] = senw1[i] + qterm[j] + sum_k senT[k][i]*q[j][k]
    // Tile: thread owns 8 consecutive i (4 f32x2 lanes) x 4 j (stride 16)
    {
        const int tx = tid & 31;       // i block
        const int ty = tid >> 5;       // 0..15
        const int i0 = tx * 8;
        float e[8];
        #pragma unroll
        for (int u = 0; u < 8; u++) e[u] = s_senw1[i0 + u];

        for (int jc = 0; jc < 8; jc++) {
            u64 acc[4][4];
            #pragma unroll
            for (int jj = 0; jj < 4; jj++)
                #pragma unroll
                for (int iv = 0; iv < 4; iv++) acc[jj][iv] = 0ull;

            #pragma unroll 2
            for (int k = 0; k < NF; k++) {
                const ulonglong2 a01 = *(const ulonglong2*)(s_senT + k*STP + i0);
                const ulonglong2 a23 = *(const ulonglong2*)(s_senT + k*STP + i0 + 4);
                #pragma unroll
                for (int jj = 0; jj < 4; jj++) {
                    const int j = jc*64 + ty + jj*16;
                    const float bv = s_q[j*QP + k];
                    const u64 b2 = pack2(bv, bv);
                    acc[jj][0] = fma2(a01.x, b2, acc[jj][0]);
                    acc[jj][1] = fma2(a01.y, b2, acc[jj][1]);
                    acc[jj][2] = fma2(a23.x, b2, acc[jj][2]);
                    acc[jj][3] = fma2(a23.y, b2, acc[jj][3]);
                }
            }
            #pragma unroll
            for (int jj = 0; jj < 4; jj++) {
                const int j = jc*64 + ty + jj*16;
                const float qt = s_qterm[j];
                float2 p;
                float4 v0, v1;
                p = unpack2(acc[jj][0]); v0.x = p.x+qt+e[0]; v0.y = p.y+qt+e[1];
                p = unpack2(acc[jj][1]); v0.z = p.x+qt+e[2]; v0.w = p.y+qt+e[3];
                p = unpack2(acc[jj][2]); v1.x = p.x+qt+e[4]; v1.y = p.y+qt+e[5];
                p = unpack2(acc[jj][3]); v1.z = p.x+qt+e[6]; v1.w = p.y+qt+e[7];
                *(float4*)(Scol + j*ND + i0)     = v0;
                *(float4*)(Scol + j*ND + i0 + 4) = v1;
            }
        }
    }
    __syncthreads();

    // ---------------- pass 2 & 3 concurrently on disjoint warp halves
    if (tid < 256) {
        // row stats (softmax axis=1, over j). thread = row i, 4-way MLP
        const int i = tid;
        float m0 = -3.0e38f, m1 = -3.0e38f, m2 = -3.0e38f, m3 = -3.0e38f;
        for (int j = 0; j < NQ; j += 4) {
            m0 = fmaxf(m0, Scol[(j+0)*ND + i]);
            m1 = fmaxf(m1, Scol[(j+1)*ND + i]);
            m2 = fmaxf(m2, Scol[(j+2)*ND + i]);
            m3 = fmaxf(m3, Scol[(j+3)*ND + i]);
        }
        const float m = fmaxf(fmaxf(m0, m1), fmaxf(m2, m3));
        float s0 = 0.f, s1 = 0.f, s2 = 0.f, s3 = 0.f;
        for (int j = 0; j < NQ; j += 4) {
            s0 += __expf(Scol[(j+0)*ND + i] - m);
            s1 += __expf(Scol[(j+1)*ND + i] - m);
            s2 += __expf(Scol[(j+2)*ND + i] - m);
            s3 += __expf(Scol[(j+3)*ND + i] - m);
        }
        s_rowmax[i] = m;
        s_rowinv[i] = 1.f / (s0 + s1 + s2 + s3);
    } else {
        // col stats (softmax axis=0, over i). warp per column
        const int lane = tid & 31, wrp = (tid >> 5) - 8;   // 0..7
        for (int j = wrp; j < NQ; j += 8) {
            const float* col = Scol + j*ND;
            float v[8];
            #pragma unroll
            for (int r = 0; r < 8; r++) v[r] = col[lane + 32*r];
            float m = v[0];
            #pragma unroll
            for (int r = 1; r < 8; r++) m = fmaxf(m, v[r]);
            #pragma unroll
            for (int o = 16; o > 0; o >>= 1) m = fmaxf(m, __shfl_xor_sync(0xffffffffu, m, o));
            float s = 0.f;
            #pragma unroll
            for (int r = 0; r < 8; r++) s += __expf(v[r] - m);
            #pragma unroll
            for (int o = 16; o > 0; o >>= 1) s += __shfl_xor_sync(0xffffffffu, s, o);
            if (lane == 0) { s_colmax[j] = m; s_colinv[j] = 1.f / s; }
        }
    }
    __syncthreads();

    // ---------------- pass 5: T[j][:] = sum_i sQ2D[i][j] * sen[i][:]  (thread = column j)
    {
        const int j = tid;
        const float4* col4 = (const float4*)(Scol + j*ND);
        u64 acc[26];
        #pragma unroll
        for (int c = 0; c < 26; c++) acc[c] = 0ull;

        #pragma unroll 2
        for (int i4 = 0; i4 < ND/4; i4++) {
            const float4 v4 = col4[i4];
            const float vv[4] = { v4.x, v4.y, v4.z, v4.w };
            #pragma unroll
            for (int u = 0; u < 4; u++) {
                const int i = i4*4 + u;
                const float qf = __expf(vv[u] - s_rowmax[i]) * s_rowinv[i];
                const u64 q2 = pack2(qf, qf);
                const ulonglong2* srow = (const ulonglong2*)(s_sen4 + i*QP);
                #pragma unroll
                for (int c = 0; c < 13; c++) {
                    const ulonglong2 sv = srow[c];
                    acc[2*c+0] = fma2(sv.x, q2, acc[2*c+0]);
                    acc[2*c+1] = fma2(sv.y, q2, acc[2*c+1]);
                }
            }
        }
        ulonglong2* tdst = (ulonglong2*)(Tg + j*QP);
        #pragma unroll
        for (int c = 0; c < 13; c++) {
            ulonglong2 v; v.x = acc[2*c]; v.y = acc[2*c+1];
            tdst[c] = v;
        }
    }
    __syncthreads();

    // ---------------- fused pass 4+6: one sweep over S computes BOTH
    //   aD2Q[i][:] = sum_j sD2Q[i][j]*query[j][:]
    //   aQ2D[i][:] = sum_j sD2Q[i][j]*T[j][:]
    // 2 threads per row i: each owns 26 features (h*26 .. h*26+25)
    {
        const int i   = tid & 255;
        const int h   = tid >> 8;
        const int off = h * 26;
        u64 a1[13], a2[13];
        #pragma unroll
        for (int c = 0; c < 13; c++) { a1[c] = 0ull; a2[c] = 0ull; }

        const float* qbase = s_q + off;
        const float* tbase = Tg  + off;

        #pragma unroll 2
        for (int j = 0; j < NQ; j++) {
            const float v = Scol[j*ND + i];                     // coalesced
            const float p = __expf(v - s_colmax[j]) * s_colinv[j];
            const u64 p2 = pack2(p, p);
            const u64* q8 = (const u64*)(qbase + j*QP);         // LDS.64 broadcast
            const u64* t8 = (const u64*)(tbase + j*QP);         // LDG.64 broadcast
            #pragma unroll
            for (int c = 0; c < 13; c++) {
                a1[c] = fma2(q8[c], p2, a1[c]);
                a2[c] = fma2(t8[c], p2, a2[c]);
            }
        }

        // ---------------- output: [sen | aD2Q | sen*aD2Q | sen*aQ2D]
        const float2* s2 = (const float2*)(s_sen4 + i*QP + off);
        float* orow = out + ((size_t)b*ND + i) * NOUT + off;

        #pragma unroll
        for (int c = 0; c < 12; c++) {
            const float2 sv = s2[c];
            const float2 x1 = unpack2(a1[c]);
            const float2 x2 = unpack2(a2[c]);
            *(float2*)(orow +   0 + 2*c) = sv;
            *(float2*)(orow +  50 + 2*c) = x1;
            *(float2*)(orow + 100 + 2*c) = make_float2(sv.x*x1.x, sv.y*x1.y);
            *(float2*)(orow + 150 + 2*c) = make_float2(sv.x*x2.x, sv.y*x2.y);
        }
        if (h == 0) {   // 13th pair only valid for first half (features 24,25)
            const int c = 12;
            const float2 sv = s2[c];
            const float2 x1 = unpack2(a1[c]);
            const float2 x2 = unpack2(a2[c]);
            *(float2*)(orow +   0 + 2*c) = sv;
            *(float2*)(orow +  50 + 2*c) = x1;
            *(float2*)(orow + 100 + 2*c) = make_float2(sv.x*x1.x, sv.y*x1.y);
            *(float2*)(orow + 150 + 2*c) = make_float2(sv.x*x2.x, sv.y*x2.y);
        }
    }
}

extern "C" void kernel_launch(void* const* d_in, const int* in_sizes, int n_in,
                              void* d_out, int out_size)
{
    const float* query = nullptr;
    const float* doc   = nullptr;
    const float* Wp    = nullptr;
    for (int i = 0; i < n_in; i++) {
        if      (in_sizes[i] == 150)       Wp    = (const float*)d_in[i];
        else if (in_sizes[i] == NQ*NF)     query = (const float*)d_in[i];
        else                               doc   = (const float*)d_in[i];
    }

    cudaFuncSetAttribute(cross_attn_kernel,
                         cudaFuncAttributeMaxDynamicSharedMemorySize, SMEM_BYTES);
    cross_attn_kernel<<<NS, 512, SMEM_BYTES>>>(query, doc, Wp, (float*)d_out);
}

// round 4
// speedup vs baseline: 1.2373x; 1.1855x over previous
#include <cuda_runtime.h>
#include <math.h>

#define NS 512   // sentences (blocks)
#define NQ 512   // queries  (j)
#define ND 256   // docs     (i)
#define NF 50    // features
#define QP 52    // padded feature stride (208 B, 16B-aligned, /16 exact)
#define STP 260  // senT / P-tile row stride (1040 B, 16B-aligned)
#define TTP 261  // transpose-tile row stride (bank-conflict-free)
#define NOUT 200

typedef unsigned long long u64;

// Global scratch (static __device__ arrays — allocation-free kernel_launch).
__device__ float g_S [67108864];  // [b][j][i] col-major S, later overwritten with E1=exp(S-colmax)
__device__ float g_E2[67108864];  // [b][i][j] row-major  E2=exp(S-rowmax)
__device__ float g_T [13631488];  // [b][j][QP]  T = sQ2D^T @ sen

#define SMEM_FLOATS (NQ*QP + ND*QP + 52*STP + 152 + 256 + 256 + 512 + 512 + 512)
#define SMEM_BYTES  (SMEM_FLOATS * 4)

__device__ __forceinline__ u64 pack2(float x, float y) {
    u64 r; asm("mov.b64 %0, {%1, %2};" : "=l"(r) : "f"(x), "f"(y)); return r;
}
__device__ __forceinline__ u64 fma2(u64 a, u64 b, u64 c) {
    u64 d; asm("fma.rn.f32x2 %0, %1, %2, %3;" : "=l"(d) : "l"(a), "l"(b), "l"(c)); return d;
}
__device__ __forceinline__ float2 unpack2(u64 v) {
    float lo, hi; asm("mov.b64 {%0, %1}, %2;" : "=f"(lo), "=f"(hi) : "l"(v));
    return make_float2(lo, hi);
}

__global__ __launch_bounds__(512, 1)
void cross_attn_kernel(const float* __restrict__ query,
                       const float* __restrict__ doc,
                       const float* __restrict__ W,
                       float* __restrict__ out)
{
    extern __shared__ float sm[];
    float* s_q      = sm;                   // [NQ][QP]  q; col50=1, col51=qterm
    float* s_sen    = s_q + NQ*QP;          // [ND][QP]  sen; pads zero
    float* s_senT   = s_sen + ND*QP;        // [52][STP] senT*w3; rows50/51=senw1/1; later P/transpose tile
    float* s_w      = s_senT + 52*STP;      // [152]
    float* s_rowmax = s_w + 152;            // [256]
    float* s_rowinv = s_rowmax + 256;       // [256]
    float* s_colmax = s_rowinv + 256;       // [512]
    float* s_colinv = s_colmax + 512;       // [512]
    float* s_red    = s_colinv + 512;       // [512]
    float* tile     = s_senT;               // alias (senT dead after pass1)

    const int tid = threadIdx.x;            // 0..511
    const int b   = blockIdx.x;
    float* Scol = g_S  + (size_t)b * NQ * ND;
    float* E2   = g_E2 + (size_t)b * ND * NQ;
    float* Tg   = g_T  + (size_t)b * NQ * QP;

    // ================= load phase =================
    if (tid < 150) s_w[tid] = W[tid];
    for (int idx = tid; idx < NQ*NF; idx += 512) {
        int j = idx / NF, k = idx - j*NF;
        s_q[j*QP + k] = query[idx];
    }
    const float* sen = doc + (size_t)b * ND * NF;
    for (int idx = tid; idx < ND*NF; idx += 512) {
        int i = idx / NF, k = idx - i*NF;
        s_sen[i*QP + k] = sen[idx];
    }
    if (tid < ND) { s_sen[tid*QP+50] = 0.f; s_sen[tid*QP+51] = 0.f; }
    __syncthreads();

    // qterm fold: s_q[j][50]=1, s_q[j][51]=qterm[j]
    {
        const int j = tid;
        float a = 0.f;
        #pragma unroll
        for (int k = 0; k < NF; k++) a += s_q[j*QP + k] * s_w[50 + k];
        s_q[j*QP + 50] = 1.0f;
        s_q[j*QP + 51] = a;
    }
    // senT rows 0..49 : sen^T * w3
    for (int idx = tid; idx < NF*ND; idx += 512) {
        int k = idx >> 8, i = idx & 255;
        s_senT[k*STP + i] = s_sen[i*QP + k] * s_w[100 + k];
    }
    // senw1 fold: senT[50][i]=senw1[i], senT[51][i]=1
    if (tid < ND) {
        const int i = tid;
        float a = 0.f;
        #pragma unroll
        for (int k = 0; k < NF; k++) a += s_sen[i*QP + k] * s_w[k];
        s_senT[50*STP + i] = a;
        s_senT[51*STP + i] = 1.0f;
    }
    __syncthreads();

    // ================= pass 1: S[j][i] = sum_{k=0..51} senT[k][i] * q[j][k] =================
    // (k=50,51 fold in senw1[i] + qterm[j]).  Thread: 8 consecutive i (4 u64) x 8 j (stride 16)
    {
        const int tx = tid & 31, ty = tid >> 5;
        const int i0 = tx * 8;
        for (int jc = 0; jc < 4; jc++) {
            u64 acc[8][4];
            #pragma unroll
            for (int jj = 0; jj < 8; jj++) {
                acc[jj][0]=0ull; acc[jj][1]=0ull; acc[jj][2]=0ull; acc[jj][3]=0ull;
            }
            #pragma unroll 2
            for (int k = 0; k < 52; k += 2) {
                const ulonglong2 a00 = *(const ulonglong2*)(s_senT + k*STP + i0);
                const ulonglong2 a01 = *(const ulonglong2*)(s_senT + k*STP + i0 + 4);
                const ulonglong2 a10 = *(const ulonglong2*)(s_senT + (k+1)*STP + i0);
                const ulonglong2 a11 = *(const ulonglong2*)(s_senT + (k+1)*STP + i0 + 4);
                #pragma unroll
                for (int jj = 0; jj < 8; jj++) {
                    const int j = jc*128 + jj*16 + ty;
                    const u64 qp = *(const u64*)(s_q + j*QP + k);  // (q_k, q_{k+1})
                    const float2 qf = unpack2(qp);
                    const u64 b0 = pack2(qf.x, qf.x);
                    const u64 b1 = pack2(qf.y, qf.y);
                    acc[jj][0] = fma2(a00.x, b0, acc[jj][0]);
                    acc[jj][1] = fma2(a00.y, b0, acc[jj][1]);
                    acc[jj][2] = fma2(a01.x, b0, acc[jj][2]);
                    acc[jj][3] = fma2(a01.y, b0, acc[jj][3]);
                    acc[jj][0] = fma2(a10.x, b1, acc[jj][0]);
                    acc[jj][1] = fma2(a10.y, b1, acc[jj][1]);
                    acc[jj][2] = fma2(a11.x, b1, acc[jj][2]);
                    acc[jj][3] = fma2(a11.y, b1, acc[jj][3]);
                }
            }
            #pragma unroll
            for (int jj = 0; jj < 8; jj++) {
                const int j = jc*128 + jj*16 + ty;
                ulonglong2 v0; v0.x = acc[jj][0]; v0.y = acc[jj][1];
                ulonglong2 v1; v1.x = acc[jj][2]; v1.y = acc[jj][3];
                *(ulonglong2*)(Scol + j*ND + i0)     = v0;
                *(ulonglong2*)(Scol + j*ND + i0 + 4) = v1;
            }
        }
    }
    __syncthreads();

    // ================= maxes (concurrent halves) =================
    if (tid < 256) {
        // rowmax over j (coalesced: lanes over i)
        const int i = tid;
        float m0 = -3.0e38f, m1 = -3.0e38f, m2 = -3.0e38f, m3 = -3.0e38f;
        for (int j = 0; j < NQ; j += 4) {
            m0 = fmaxf(m0, Scol[(j+0)*ND + i]);
            m1 = fmaxf(m1, Scol[(j+1)*ND + i]);
            m2 = fmaxf(m2, Scol[(j+2)*ND + i]);
            m3 = fmaxf(m3, Scol[(j+3)*ND + i]);
        }
        s_rowmax[i] = fmaxf(fmaxf(m0, m1), fmaxf(m2, m3));
    } else {
        // colmax over i (warp per column)
        const int lane = tid & 31, w2 = (tid >> 5) - 8;  // 0..7
        for (int c = 0; c < 64; c++) {
            const int j = w2 + c*8;
            const float* col = Scol + j*ND;
            float m = -3.0e38f;
            #pragma unroll
            for (int r = 0; r < 8; r++) m = fmaxf(m, col[lane + 32*r]);
            #pragma unroll
            for (int o = 16; o > 0; o >>= 1) m = fmaxf(m, __shfl_xor_sync(0xffffffffu, m, o));
            if (lane == 0) s_colmax[j] = m;
        }
    }
    __syncthreads();

    // ================= sub-pass B: E2 = exp(S - rowmax) -> row-major (tiled transpose), rowsums =========
    {
        const int i = tid & 255, hh = tid >> 8;
        const int lane = tid & 31, w = tid >> 5;
        const int rr = lane >> 3, f4 = lane & 7;
        float rsum = 0.f;
        const float rm = s_rowmax[i];
        for (int jc = 0; jc < 16; jc++) {
            // step 1: coalesced read + exp -> tile[j'][i]
            #pragma unroll
            for (int jj = 0; jj < 16; jj++) {
                const int jp = hh*16 + jj;
                const float v = Scol[(jc*32 + jp)*ND + i];
                const float e = __expf(v - rm);
                rsum += e;
                tile[jp*TTP + i] = e;
            }
            __syncthreads();
            // step 2: coalesced row-major write-out
            #pragma unroll
            for (int it = 0; it < 4; it++) {
                const int row = it*64 + w*4 + rr;
                float4 v;
                v.x = tile[(f4*4+0)*TTP + row];
                v.y = tile[(f4*4+1)*TTP + row];
                v.z = tile[(f4*4+2)*TTP + row];
                v.w = tile[(f4*4+3)*TTP + row];
                *(float4*)(E2 + row*NQ + jc*32 + f4*4) = v;
            }
            __syncthreads();
        }
        s_red[tid] = rsum;
    }
    __syncthreads();
    if (tid < 256) s_rowinv[tid] = 1.0f / (s_red[tid] + s_red[tid + 256]);

    // ================= sub-pass A: overwrite S with E1 = exp(S - colmax), colsums =================
    {
        const int lane = tid & 31, w = tid >> 5;   // 16 warps x 32 cols
        for (int c = 0; c < 32; c++) {
            const int j = w + c*16;
            float* col = Scol + j*ND;
            const float cm = s_colmax[j];
            float e[8]; float s = 0.f;
            #pragma unroll
            for (int r = 0; r < 8; r++) { e[r] = __expf(col[lane + 32*r] - cm); s += e[r]; }
            #pragma unroll
            for (int r = 0; r < 8; r++) col[lane + 32*r] = e[r];
            #pragma unroll
            for (int o = 16; o > 0; o >>= 1) s += __shfl_xor_sync(0xffffffffu, s, o);
            if (lane == 0) s_colinv[j] = 1.0f / s;
        }
    }
    __syncthreads();

    // ================= pass 5: T[j][k] = sum_i (E2[i][j]*rowinv[i]) * sen[i][k] =================
    // thread: 2 columns (j, j+256) x 28-feature half (overlapping halves 0..27 / 24..51)
    {
        const int jp = tid >> 1, h = tid & 1;
        const int koff = h ? 24 : 0;
        const int j0 = jp, j1 = jp + 256;
        u64 accA[14], accB[14];
        #pragma unroll
        for (int d = 0; d < 14; d++) { accA[d] = 0ull; accB[d] = 0ull; }

        #pragma unroll 2
        for (int i = 0; i < ND; i++) {
            const float rinv = s_rowinv[i];
            const float p0 = E2[i*NQ + j0] * rinv;
            const float p1 = E2[i*NQ + j1] * rinv;
            const u64 b0 = pack2(p0, p0);
            const u64 b1 = pack2(p1, p1);
            const ulonglong2* srow = (const ulonglong2*)(s_sen + i*QP + koff);
            #pragma unroll
            for (int c = 0; c < 7; c++) {
                const ulonglong2 sv = srow[c];
                accA[2*c+0] = fma2(sv.x, b0, accA[2*c+0]);
                accA[2*c+1] = fma2(sv.y, b0, accA[2*c+1]);
                accB[2*c+0] = fma2(sv.x, b1, accB[2*c+0]);
                accB[2*c+1] = fma2(sv.y, b1, accB[2*c+1]);
            }
        }
        if (h == 0) {   // write features 0..27
            #pragma unroll
            for (int c = 0; c < 7; c++) {
                ulonglong2 vA; vA.x = accA[2*c]; vA.y = accA[2*c+1];
                ulonglong2 vB; vB.x = accB[2*c]; vB.y = accB[2*c+1];
                *(ulonglong2*)(Tg + j0*QP + 4*c) = vA;
                *(ulonglong2*)(Tg + j1*QP + 4*c) = vB;
            }
        } else {        // write features 28..51 (skip overlap 24..27)
            #pragma unroll
            for (int c = 0; c < 6; c++) {
                ulonglong2 vA; vA.x = accA[2+2*c]; vA.y = accA[3+2*c];
                ulonglong2 vB; vB.x = accB[2+2*c]; vB.y = accB[3+2*c];
                *(ulonglong2*)(Tg + j0*QP + 28 + 4*c) = vA;
                *(ulonglong2*)(Tg + j1*QP + 28 + 4*c) = vB;
            }
        }
    }
    __syncthreads();

    // ================= fused pass 4+6: staged-P register-tiled GEMM =================
    //   aD2Q[i][k] = sum_j P[i][j] * q[j][k],  aQ2D[i][k] = sum_j P[i][j] * T[j][k]
    //   P[i][j] = E1[j][i] * colinv[j] (staged per 32-j chunk into SMEM tile)
    {
        const int ig = tid >> 4, kg = tid & 15;        // 32 i-groups x 16 (13 active) k-quads
        const int i0 = ig * 8;
        const int si = tid & 255, hh = tid >> 8;
        u64 ac1[4][4], ac2[4][4];                      // [k 0..3][i-pair 0..3]
        #pragma unroll
        for (int k = 0; k < 4; k++)
            #pragma unroll
            for (int m = 0; m < 4; m++) { ac1[k][m] = 0ull; ac2[k][m] = 0ull; }

        for (int jc = 0; jc < 16; jc++) {
            // stage P chunk (colinv folded)
            #pragma unroll
            for (int jj = 0; jj < 16; jj++) {
                const int jp = hh*16 + jj, jg = jc*32 + jp;
                tile[jp*STP + si] = Scol[jg*ND + si] * s_colinv[jg];
            }
            __syncthreads();
            if (kg < 13) {
                #pragma unroll 2
                for (int jj = 0; jj < 32; jj++) {
                    const int j = jc*32 + jj;
                    const ulonglong2 p01 = *(const ulonglong2*)(tile + jj*STP + i0);
                    const ulonglong2 p23 = *(const ulonglong2*)(tile + jj*STP + i0 + 4);
                    const u64 pa0 = p01.x, pa1 = p01.y, pa2 = p23.x, pa3 = p23.y;
                    const float4 qv = *(const float4*)(s_q + j*QP + kg*4);
                    const float4 tv = *(const float4*)(Tg  + j*QP + kg*4);
                    u64 bb;
                    bb = pack2(qv.x, qv.x);
                    ac1[0][0]=fma2(pa0,bb,ac1[0][0]); ac1[0][1]=fma2(pa1,bb,ac1[0][1]);
                    ac1[0][2]=fma2(pa2,bb,ac1[0][2]); ac1[0][3]=fma2(pa3,bb,ac1[0][3]);
                    bb = pack2(qv.y, qv.y);
                    ac1[1][0]=fma2(pa0,bb,ac1[1][0]); ac1[1][1]=fma2(pa1,bb,ac1[1][1]);
                    ac1[1][2]=fma2(pa2,bb,ac1[1][2]); ac1[1][3]=fma2(pa3,bb,ac1[1][3]);
                    bb = pack2(qv.z, qv.z);
                    ac1[2][0]=fma2(pa0,bb,ac1[2][0]); ac1[2][1]=fma2(pa1,bb,ac1[2][1]);
                    ac1[2][2]=fma2(pa2,bb,ac1[2][2]); ac1[2][3]=fma2(pa3,bb,ac1[2][3]);
                    bb = pack2(qv.w, qv.w);
                    ac1[3][0]=fma2(pa0,bb,ac1[3][0]); ac1[3][1]=fma2(pa1,bb,ac1[3][1]);
                    ac1[3][2]=fma2(pa2,bb,ac1[3][2]); ac1[3][3]=fma2(pa3,bb,ac1[3][3]);
                    bb = pack2(tv.x, tv.x);
                    ac2[0][0]=fma2(pa0,bb,ac2[0][0]); ac2[0][1]=fma2(pa1,bb,ac2[0][1]);
                    ac2[0][2]=fma2(pa2,bb,ac2[0][2]); ac2[0][3]=fma2(pa3,bb,ac2[0][3]);
                    bb = pack2(tv.y, tv.y);
                    ac2[1][0]=fma2(pa0,bb,ac2[1][0]); ac2[1][1]=fma2(pa1,bb,ac2[1][1]);
                    ac2[1][2]=fma2(pa2,bb,ac2[1][2]); ac2[1][3]=fma2(pa3,bb,ac2[1][3]);
                    bb = pack2(tv.z, tv.z);
                    ac2[2][0]=fma2(pa0,bb,ac2[2][0]); ac2[2][1]=fma2(pa1,bb,ac2[2][1]);
                    ac2[2][2]=fma2(pa2,bb,ac2[2][2]); ac2[2][3]=fma2(pa3,bb,ac2[2][3]);
                    bb = pack2(tv.w, tv.w);
                    ac2[3][0]=fma2(pa0,bb,ac2[3][0]); ac2[3][1]=fma2(pa1,bb,ac2[3][1]);
                    ac2[3][2]=fma2(pa2,bb,ac2[3][2]); ac2[3][3]=fma2(pa3,bb,ac2[3][3]);
                }
            }
            __syncthreads();
        }

        // ---------------- epilogue: [sen | aD2Q | sen*aD2Q | sen*aQ2D] ----------------
        if (kg < 13) {
            #pragma unroll
            for (int m = 0; m < 4; m++) {
                float2 u1[4], u2[4];
                #pragma unroll
                for (int k = 0; k < 4; k++) { u1[k] = unpack2(ac1[k][m]); u2[k] = unpack2(ac2[k][m]); }
                #pragma unroll
                for (int par = 0; par < 2; par++) {
                    const int i = i0 + 2*m + par;
                    float a1v[4], a2v[4];
                    #pragma unroll
                    for (int k = 0; k < 4; k++) {
                        a1v[k] = par ? u1[k].y : u1[k].x;
                        a2v[k] = par ? u2[k].y : u2[k].x;
                    }
                    const float4 sv = *(const float4*)(s_sen + i*QP + kg*4);
                    float* orow = out + ((size_t)b*ND + i) * NOUT;
                    if (kg < 12) {
                        *(float4*)(orow + kg*4) = sv;
                        *(float2*)(orow +  50 + kg*4) = make_float2(a1v[0], a1v[1]);
                        *(float2*)(orow +  52 + kg*4) = make_float2(a1v[2], a1v[3]);
                        float4 p2; p2.x = sv.x*a1v[0]; p2.y = sv.y*a1v[1];
                                   p2.z = sv.z*a1v[2]; p2.w = sv.w*a1v[3];
                        *(float4*)(orow + 100 + kg*4) = p2;
                        *(float2*)(orow + 150 + kg*4) = make_float2(sv.x*a2v[0], sv.y*a2v[1]);
                        *(float2*)(orow + 152 + kg*4) = make_float2(sv.z*a2v[2], sv.w*a2v[3]);
                    } else {  // kg == 12: features 48,49 only
                        *(float2*)(orow +  48) = make_float2(sv.x, sv.y);
                        *(float2*)(orow +  98) = make_float2(a1v[0], a1v[1]);
                        *(float2*)(orow + 148) = make_float2(sv.x*a1v[0], sv.y*a1v[1]);
                        *(float2*)(orow + 198) = make_float2(sv.x*a2v[0], sv.y*a2v[1]);
                    }
                }
            }
        }
    }
}

extern "C" void kernel_launch(void* const* d_in, const int* in_sizes, int n_in,
                              void* d_out, int out_size)
{
    const float* query = nullptr;
    const float* doc   = nullptr;
    const float* Wp    = nullptr;
    for (int i = 0; i < n_in; i++) {
        if      (in_sizes[i] == 150)       Wp    = (const float*)d_in[i];
        else if (in_sizes[i] == NQ*NF)     query = (const float*)d_in[i];
        else                               doc   = (const float*)d_in[i];
    }

    cudaFuncSetAttribute(cross_attn_kernel,
                         cudaFuncAttributeMaxDynamicSharedMemorySize, SMEM_BYTES);
    cross_attn_kernel<<<NS, 512, SMEM_BYTES>>>(query, doc, Wp, (float*)d_out);
}